// round 8
// baseline (speedup 1.0000x reference)
#include <cuda_runtime.h>
#include <math_constants.h>

// Output spatial: 28x28, batch 8, out channels 256.
#define HW   28
#define NB   8
#define PLANE (HW*HW)        // 784
#define PLANE4 (PLANE/4)     // 196

// Pooled scratch (channel-tiling means we pool once, reuse across replicas).
__device__ float g_p1[NB*128*PLANE]; // pool2  of (8,128,56,56)
__device__ float g_p2[NB*64 *PLANE]; // pool4  of (8,64,112,112)
__device__ float g_p3[NB*32 *PLANE]; // pool8  of (8,32,224,224)
__device__ float g_p4[NB*16 *PLANE]; // pool16 of (8,16,448,448)

// Block-range dispatch (256 threads/block), 8x LDG.128 per thread everywhere:
// Seg A: k=16, t4, 8 lanes/output, 2 rows each : 100352*8/256 = 3136 blocks
// Seg B: k=8,  t3, 2 lanes/output, 4 rows each : 200704*2/256 = 1568 blocks
// Seg C: k=4,  t2, thread / 2 outputs          : 200704/256   =  784 blocks
// Seg D: k=2,  t1, thread / 2x4 output block   : 100352/256   =  392 blocks
#define A_BLOCKS 3136
#define B_BLOCKS 1568
#define C_BLOCKS 784
#define D_BLOCKS 392
#define POOL_BLOCKS (A_BLOCKS + B_BLOCKS + C_BLOCKS + D_BLOCKS)

__device__ __forceinline__ float max4(float4 v) {
    return fmaxf(fmaxf(v.x, v.y), fmaxf(v.z, v.w));
}

__global__ void __launch_bounds__(256) fused_pool_kernel(
    const float* __restrict__ t1, const float* __restrict__ t2,
    const float* __restrict__ t3, const float* __restrict__ t4)
{
    int bid = blockIdx.x;
    int tid = threadIdx.x;

    if (bid < A_BLOCKS) {
        // ---- k=16 pool of (8,16,448,448): 8 lanes/output, rows r and r+8 ----
        int t = bid * 256 + tid;
        int oidx = t >> 3;                        // 0..100351
        int r = t & 7;
        int w = oidx % HW;
        int h = (oidx / HW) % HW;
        long bc = oidx / PLANE;                   // b*16 + c
        const float* p0 = t4 + (bc * 448 + (long)(h * 16 + r)) * 448 + (long)w * 16;
        const float* p1 = p0 + 8L * 448;          // row r+8
        float4 v0 = __ldcs(reinterpret_cast<const float4*>(p0));
        float4 v1 = __ldcs(reinterpret_cast<const float4*>(p0 + 4));
        float4 v2 = __ldcs(reinterpret_cast<const float4*>(p0 + 8));
        float4 v3 = __ldcs(reinterpret_cast<const float4*>(p0 + 12));
        float4 v4 = __ldcs(reinterpret_cast<const float4*>(p1));
        float4 v5 = __ldcs(reinterpret_cast<const float4*>(p1 + 4));
        float4 v6 = __ldcs(reinterpret_cast<const float4*>(p1 + 8));
        float4 v7 = __ldcs(reinterpret_cast<const float4*>(p1 + 12));
        float m = fmaxf(fmaxf(fmaxf(max4(v0), max4(v1)), fmaxf(max4(v2), max4(v3))),
                        fmaxf(fmaxf(max4(v4), max4(v5)), fmaxf(max4(v6), max4(v7))));
        #pragma unroll
        for (int k = 4; k >= 1; k >>= 1)          // reduce within 8-lane group
            m = fmaxf(m, __shfl_xor_sync(0xffffffffu, m, k));
        if (r == 0) g_p4[oidx] = m;
        return;
    }
    bid -= A_BLOCKS;

    if (bid < B_BLOCKS) {
        // ---- k=8 pool of (8,32,224,224): 2 lanes/output, 4 rows each ----
        int t = bid * 256 + tid;
        int oidx = t >> 1;                        // 0..200703
        int g = t & 1;                            // row-quad within window
        int w = oidx % HW;
        int h = (oidx / HW) % HW;
        long bc = oidx / PLANE;                   // b*32 + c
        const float* p = t3 + (bc * 224 + (long)(h * 8 + 4 * g)) * 224 + (long)w * 8;
        float4 v0 = __ldcs(reinterpret_cast<const float4*>(p));
        float4 v1 = __ldcs(reinterpret_cast<const float4*>(p + 4));
        float4 v2 = __ldcs(reinterpret_cast<const float4*>(p + 224));
        float4 v3 = __ldcs(reinterpret_cast<const float4*>(p + 228));
        float4 v4 = __ldcs(reinterpret_cast<const float4*>(p + 448));
        float4 v5 = __ldcs(reinterpret_cast<const float4*>(p + 452));
        float4 v6 = __ldcs(reinterpret_cast<const float4*>(p + 672));
        float4 v7 = __ldcs(reinterpret_cast<const float4*>(p + 676));
        float m = fmaxf(fmaxf(fmaxf(max4(v0), max4(v1)), fmaxf(max4(v2), max4(v3))),
                        fmaxf(fmaxf(max4(v4), max4(v5)), fmaxf(max4(v6), max4(v7))));
        m = fmaxf(m, __shfl_xor_sync(0xffffffffu, m, 1));
        if (g == 0) g_p3[oidx] = m;
        return;
    }
    bid -= B_BLOCKS;

    if (bid < C_BLOCKS) {
        // ---- k=4 pool of (8,64,112,112): thread per 2 horizontal outputs ----
        int t = bid * 256 + tid;                  // 0..200703 (output pairs)
        constexpr int PPLANE = PLANE / 2;         // 392 pairs per plane
        int s  = t % PPLANE;
        int w2 = s % (HW / 2);                    // pair col 0..13
        int h  = s / (HW / 2);
        long bc = t / PPLANE;                     // b*64 + c
        const float* p = t2 + (bc * 112 + (long)(h * 4)) * 112 + (long)w2 * 8;
        float4 a0 = __ldcs(reinterpret_cast<const float4*>(p));
        float4 b0 = __ldcs(reinterpret_cast<const float4*>(p + 4));
        float4 a1 = __ldcs(reinterpret_cast<const float4*>(p + 112));
        float4 b1 = __ldcs(reinterpret_cast<const float4*>(p + 116));
        float4 a2 = __ldcs(reinterpret_cast<const float4*>(p + 224));
        float4 b2 = __ldcs(reinterpret_cast<const float4*>(p + 228));
        float4 a3 = __ldcs(reinterpret_cast<const float4*>(p + 336));
        float4 b3 = __ldcs(reinterpret_cast<const float4*>(p + 340));
        float2 o;
        o.x = fmaxf(fmaxf(max4(a0), max4(a1)), fmaxf(max4(a2), max4(a3)));
        o.y = fmaxf(fmaxf(max4(b0), max4(b1)), fmaxf(max4(b2), max4(b3)));
        *reinterpret_cast<float2*>(g_p2 + bc * PLANE + h * HW + w2 * 2) = o;
        return;
    }
    bid -= C_BLOCKS;

    {
        // ---- k=2 pool of (8,128,56,56): thread per 2x4 output block ----
        int t = bid * 256 + tid;                  // 0..100351
        constexpr int QROW = HW / 4;              // 7 quads per output row
        constexpr int QPLANE = QROW * (HW / 2);   // 98 blocks per plane
        int s  = t % QPLANE;
        int w4 = s % QROW;                        // quad col 0..6
        int h2 = s / QROW;                        // output row-pair 0..13
        long bc = t / QPLANE;                     // b*128 + c
        const float* p = t1 + (bc * 56 + (long)(h2 * 4)) * 56 + (long)w4 * 8;
        // 4 input rows x 8 cols
        float4 r0a = __ldcs(reinterpret_cast<const float4*>(p));
        float4 r0b = __ldcs(reinterpret_cast<const float4*>(p + 4));
        float4 r1a = __ldcs(reinterpret_cast<const float4*>(p + 56));
        float4 r1b = __ldcs(reinterpret_cast<const float4*>(p + 60));
        float4 r2a = __ldcs(reinterpret_cast<const float4*>(p + 112));
        float4 r2b = __ldcs(reinterpret_cast<const float4*>(p + 116));
        float4 r3a = __ldcs(reinterpret_cast<const float4*>(p + 168));
        float4 r3b = __ldcs(reinterpret_cast<const float4*>(p + 172));
        float4 o0, o1;   // output rows 2*h2 and 2*h2+1, 4 outputs each
        o0.x = fmaxf(fmaxf(r0a.x, r0a.y), fmaxf(r1a.x, r1a.y));
        o0.y = fmaxf(fmaxf(r0a.z, r0a.w), fmaxf(r1a.z, r1a.w));
        o0.z = fmaxf(fmaxf(r0b.x, r0b.y), fmaxf(r1b.x, r1b.y));
        o0.w = fmaxf(fmaxf(r0b.z, r0b.w), fmaxf(r1b.z, r1b.w));
        o1.x = fmaxf(fmaxf(r2a.x, r2a.y), fmaxf(r3a.x, r3a.y));
        o1.y = fmaxf(fmaxf(r2a.z, r2a.w), fmaxf(r3a.z, r3a.w));
        o1.z = fmaxf(fmaxf(r2b.x, r2b.y), fmaxf(r3b.x, r3b.y));
        o1.w = fmaxf(fmaxf(r2b.z, r2b.w), fmaxf(r3b.z, r3b.w));
        float* q = g_p1 + bc * PLANE + (long)(h2 * 2) * HW + w4 * 4;
        *reinterpret_cast<float4*>(q) = o0;
        *reinterpret_cast<float4*>(q + HW) = o1;
    }
}

__global__ void __launch_bounds__(256) combine_kernel(
    const float* __restrict__ ff, float* __restrict__ out)
{
    constexpr int TOTAL4 = NB * 256 * PLANE4;   // 401408
    constexpr int HALF4  = TOTAL4 / 2;          // 200704 (= 4 batches worth)
    int idx4 = blockIdx.x * blockDim.x + threadIdx.x;
    if (idx4 >= HALF4) return;

    int s = idx4 % PLANE4;
    int c = (idx4 / PLANE4) % 256;
    int b = idx4 / (PLANE4 * 256);              // 0..3; second element is b+4

    const float4* P1 = reinterpret_cast<const float4*>(g_p1);
    const float4* P2 = reinterpret_cast<const float4*>(g_p2);
    const float4* P3 = reinterpret_cast<const float4*>(g_p3);
    const float4* P4 = reinterpret_cast<const float4*>(g_p4);
    const float4* FF = reinterpret_cast<const float4*>(ff);

    int i1 = (b * 128 + (c & 127)) * PLANE4 + s;
    int i2 = (b * 64  + (c & 63))  * PLANE4 + s;
    int i3 = (b * 32  + (c & 31))  * PLANE4 + s;
    int i4 = (b * 16  + (c & 15))  * PLANE4 + s;

    // Front-batch all 10 loads (2 output elements: batches b and b+4).
    float4 a0 = P1[i1],                     a1 = P1[i1 + 4*128*PLANE4];
    float4 d0 = P2[i2],                     d1 = P2[i2 + 4*64 *PLANE4];
    float4 e0 = P3[i3],                     e1 = P3[i3 + 4*32 *PLANE4];
    float4 g0 = P4[i4],                     g1 = P4[i4 + 4*16 *PLANE4];
    float4 f0 = __ldcs(FF + idx4),          f1 = __ldcs(FF + idx4 + HALF4);

    float4 o0, o1;
    o0.x = fmaxf(a0.x + d0.x + e0.x + g0.x + f0.x, 0.0f);
    o0.y = fmaxf(a0.y + d0.y + e0.y + g0.y + f0.y, 0.0f);
    o0.z = fmaxf(a0.z + d0.z + e0.z + g0.z + f0.z, 0.0f);
    o0.w = fmaxf(a0.w + d0.w + e0.w + g0.w + f0.w, 0.0f);
    o1.x = fmaxf(a1.x + d1.x + e1.x + g1.x + f1.x, 0.0f);
    o1.y = fmaxf(a1.y + d1.y + e1.y + g1.y + f1.y, 0.0f);
    o1.z = fmaxf(a1.z + d1.z + e1.z + g1.z + f1.z, 0.0f);
    o1.w = fmaxf(a1.w + d1.w + e1.w + g1.w + f1.w, 0.0f);
    reinterpret_cast<float4*>(out)[idx4] = o0;
    reinterpret_cast<float4*>(out)[idx4 + HALF4] = o1;
}

extern "C" void kernel_launch(void* const* d_in, const int* in_sizes, int n_in,
                              void* d_out, int out_size) {
    // Map inputs by unique element count (robust to ordering).
    const float *t1 = nullptr, *t2 = nullptr, *t3 = nullptr, *t4 = nullptr, *ff = nullptr;
    for (int i = 0; i < n_in; i++) {
        switch (in_sizes[i]) {
            case 8*128*56*56:   t1 = (const float*)d_in[i]; break;   // 3211264
            case 8*64*112*112:  t2 = (const float*)d_in[i]; break;   // 6422528
            case 8*32*224*224:  t3 = (const float*)d_in[i]; break;   // 12845056
            case 8*16*448*448:  t4 = (const float*)d_in[i]; break;   // 25690112
            case 8*256*28*28:   ff = (const float*)d_in[i]; break;   // 1605632
        }
    }

    fused_pool_kernel<<<POOL_BLOCKS, 256>>>(t1, t2, t3, t4);

    constexpr int HALF4 = (NB * 256 * PLANE4) / 2;   // 200704
    combine_kernel<<<(HALF4 + 255) / 256, 256>>>(ff, (float*)d_out);
}

// round 11
// speedup vs baseline: 1.1139x; 1.1139x over previous
#include <cuda_runtime.h>
#include <math_constants.h>

// Output spatial: 28x28, batch 8, out channels 256.
#define HW   28
#define NB   8
#define PLANE (HW*HW)        // 784
#define PLANE4 (PLANE/4)     // 196

// Pooled scratch (channel-tiling means we pool once, reuse across replicas).
__device__ float g_p1[NB*128*PLANE]; // pool2  of (8,128,56,56)
__device__ float g_p2[NB*64 *PLANE]; // pool4  of (8,64,112,112)
__device__ float g_p3[NB*32 *PLANE]; // pool8  of (8,32,224,224)
__device__ float g_p4[NB*16 *PLANE]; // pool16 of (8,16,448,448)

// Block-range dispatch (256 threads/block). All requests lane-contiguous
// (100% sector efficiency): consecutive lanes read consecutive 16B.
// Seg A: k=16, t4, warp/output (2 loads, rows split 0-7/8-15): 100352*32/256 = 12544
// Seg B: k=8,  t3, warp/4 outputs (16-lane windows, 2 loads) : 200704*8/256  =  6272
// Seg C: k=4,  t2, thread/output, 4 row-loads                : 401408/256    =  1568
// Seg D: k=2,  t1, thread/2 outputs, 2 row-loads             : 401408/256    =  1568
#define A_BLOCKS 12544
#define B_BLOCKS 6272
#define C_BLOCKS 1568
#define D_BLOCKS 1568
#define POOL_BLOCKS (A_BLOCKS + B_BLOCKS + C_BLOCKS + D_BLOCKS)

__device__ __forceinline__ float max4(float4 v) {
    return fmaxf(fmaxf(v.x, v.y), fmaxf(v.z, v.w));
}

__global__ void __launch_bounds__(256) fused_pool_kernel(
    const float* __restrict__ t1, const float* __restrict__ t2,
    const float* __restrict__ t3, const float* __restrict__ t4)
{
    int bid = blockIdx.x;
    int tid = threadIdx.x;

    if (bid < A_BLOCKS) {
        // ---- k=16 pool of (8,16,448,448): one warp per output ----
        // Lane l covers 16B chunk (l&3) of window rows (l>>2) and (l>>2)+8.
        // Each LDG.128: 8 rows x 64B dense, 64B-aligned -> full sectors.
        int t = bid * 256 + tid;
        int oidx = t >> 5;                        // 0..100351
        int lane = t & 31;
        int r  = lane >> 2;                       // 0..7
        int ch = lane & 3;                        // 0..3
        int w = oidx % HW;
        int h = (oidx / HW) % HW;
        long bc = oidx / PLANE;                   // b*16 + c
        const float* base = t4 + (bc * 448 + (long)(h * 16 + r)) * 448
                               + (long)w * 16 + ch * 4;
        float4 v0 = __ldcs(reinterpret_cast<const float4*>(base));
        float4 v1 = __ldcs(reinterpret_cast<const float4*>(base + 8L * 448));
        float m = fmaxf(max4(v0), max4(v1));
        #pragma unroll
        for (int k = 16; k >= 1; k >>= 1)
            m = fmaxf(m, __shfl_xor_sync(0xffffffffu, m, k));
        if (lane == 0) g_p4[oidx] = m;
        return;
    }
    bid -= A_BLOCKS;

    if (bid < B_BLOCKS) {
        // ---- k=8 pool of (8,32,224,224): warp covers 4 outputs ----
        // Half-warp h2 handles outputs obase+h2 and obase+h2+2.
        // Lane (within 16): row (ll>>1), 16B chunk (ll&1) -> 32B-aligned runs.
        int t = bid * 256 + tid;
        int obase = (t >> 5) * 4;                 // 0..200700, multiple of 4
        int lane = t & 31;
        int h2 = lane >> 4;                       // 0 or 1
        int ll = lane & 15;
        int r  = ll >> 1;                         // 0..7
        int ch = ll & 1;                          // 0..1
        int o0 = obase + h2;                      // second output is o0+2
        int w = o0 % HW;                          // 28 % 4 == 0: all 4 share h,bc
        int h = (o0 / HW) % HW;
        long bc = o0 / PLANE;                     // b*32 + c
        const float* base = t3 + (bc * 224 + (long)(h * 8 + r)) * 224
                               + (long)w * 8 + ch * 4;
        float4 v0 = __ldcs(reinterpret_cast<const float4*>(base));       // o0
        float4 v1 = __ldcs(reinterpret_cast<const float4*>(base + 16));  // o0+2
        float m0 = max4(v0);
        float m1 = max4(v1);
        #pragma unroll
        for (int k = 8; k >= 1; k >>= 1) {        // reduce within 16-lane group
            m0 = fmaxf(m0, __shfl_xor_sync(0xffffffffu, m0, k));
            m1 = fmaxf(m1, __shfl_xor_sync(0xffffffffu, m1, k));
        }
        if (ll == 0) {
            g_p3[o0]     = m0;
            g_p3[o0 + 2] = m1;
        }
        return;
    }
    bid -= B_BLOCKS;

    if (bid < C_BLOCKS) {
        // ---- k=4 pool of (8,64,112,112): thread per output, 4 row-loads ----
        // Consecutive threads -> consecutive 16B within each input row.
        int oidx = bid * 256 + tid;               // 0..401407
        int w = oidx % HW;
        int h = (oidx / HW) % HW;
        long bc = oidx / PLANE;                   // b*64 + c
        const float* p = t2 + (bc * 112 + (long)(h * 4)) * 112 + (long)w * 4;
        float4 v0 = __ldcs(reinterpret_cast<const float4*>(p));
        float4 v1 = __ldcs(reinterpret_cast<const float4*>(p + 112));
        float4 v2 = __ldcs(reinterpret_cast<const float4*>(p + 224));
        float4 v3 = __ldcs(reinterpret_cast<const float4*>(p + 336));
        g_p2[oidx] = fmaxf(fmaxf(max4(v0), max4(v1)), fmaxf(max4(v2), max4(v3)));
        return;
    }
    bid -= C_BLOCKS;

    {
        // ---- k=2 pool of (8,128,56,56): thread per 2 horizontal outputs ----
        // Thread reads 16B of each of 2 input rows; lanes contiguous in-row.
        int pi = bid * 256 + tid;                 // 0..401407 (output pairs)
        constexpr int HALFROW = HW / 2;           // 14 pairs per output row
        constexpr int PPLANE = PLANE / 2;         // 392 pairs per plane
        int w2 = pi % HALFROW;
        int h  = (pi / HALFROW) % HW;
        long bc = pi / PPLANE;                    // b*128 + c
        const float* p = t1 + (bc * 56 + (long)(h * 2)) * 56 + (long)w2 * 4;
        float4 a = __ldcs(reinterpret_cast<const float4*>(p));
        float4 b = __ldcs(reinterpret_cast<const float4*>(p + 56));
        float2 o;
        o.x = fmaxf(fmaxf(a.x, a.y), fmaxf(b.x, b.y));
        o.y = fmaxf(fmaxf(a.z, a.w), fmaxf(b.z, b.w));
        *reinterpret_cast<float2*>(g_p1 + bc * PLANE + h * HW + w2 * 2) = o;
    }
}

__global__ void __launch_bounds__(256) combine_kernel(
    const float* __restrict__ ff, float* __restrict__ out)
{
    constexpr int TOTAL4 = NB * 256 * PLANE4;   // 401408
    constexpr int HALF4  = TOTAL4 / 2;          // 200704 (= 4 batches worth)
    int idx4 = blockIdx.x * blockDim.x + threadIdx.x;
    if (idx4 >= HALF4) return;

    int s = idx4 % PLANE4;
    int c = (idx4 / PLANE4) % 256;
    int b = idx4 / (PLANE4 * 256);              // 0..3; second element is b+4

    const float4* P1 = reinterpret_cast<const float4*>(g_p1);
    const float4* P2 = reinterpret_cast<const float4*>(g_p2);
    const float4* P3 = reinterpret_cast<const float4*>(g_p3);
    const float4* P4 = reinterpret_cast<const float4*>(g_p4);
    const float4* FF = reinterpret_cast<const float4*>(ff);

    int i1 = (b * 128 + (c & 127)) * PLANE4 + s;
    int i2 = (b * 64  + (c & 63))  * PLANE4 + s;
    int i3 = (b * 32  + (c & 31))  * PLANE4 + s;
    int i4 = (b * 16  + (c & 15))  * PLANE4 + s;

    // Front-batch all 10 loads (2 output elements: batches b and b+4).
    float4 a0 = P1[i1],                     a1 = P1[i1 + 4*128*PLANE4];
    float4 d0 = P2[i2],                     d1 = P2[i2 + 4*64 *PLANE4];
    float4 e0 = P3[i3],                     e1 = P3[i3 + 4*32 *PLANE4];
    float4 g0 = P4[i4],                     g1 = P4[i4 + 4*16 *PLANE4];
    float4 f0 = __ldcs(FF + idx4),          f1 = __ldcs(FF + idx4 + HALF4);

    float4 o0, o1;
    o0.x = fmaxf(a0.x + d0.x + e0.x + g0.x + f0.x, 0.0f);
    o0.y = fmaxf(a0.y + d0.y + e0.y + g0.y + f0.y, 0.0f);
    o0.z = fmaxf(a0.z + d0.z + e0.z + g0.z + f0.z, 0.0f);
    o0.w = fmaxf(a0.w + d0.w + e0.w + g0.w + f0.w, 0.0f);
    o1.x = fmaxf(a1.x + d1.x + e1.x + g1.x + f1.x, 0.0f);
    o1.y = fmaxf(a1.y + d1.y + e1.y + g1.y + f1.y, 0.0f);
    o1.z = fmaxf(a1.z + d1.z + e1.z + g1.z + f1.z, 0.0f);
    o1.w = fmaxf(a1.w + d1.w + e1.w + g1.w + f1.w, 0.0f);
    reinterpret_cast<float4*>(out)[idx4] = o0;
    reinterpret_cast<float4*>(out)[idx4 + HALF4] = o1;
}

extern "C" void kernel_launch(void* const* d_in, const int* in_sizes, int n_in,
                              void* d_out, int out_size) {
    // Map inputs by unique element count (robust to ordering).
    const float *t1 = nullptr, *t2 = nullptr, *t3 = nullptr, *t4 = nullptr, *ff = nullptr;
    for (int i = 0; i < n_in; i++) {
        switch (in_sizes[i]) {
            case 8*128*56*56:   t1 = (const float*)d_in[i]; break;   // 3211264
            case 8*64*112*112:  t2 = (const float*)d_in[i]; break;   // 6422528
            case 8*32*224*224:  t3 = (const float*)d_in[i]; break;   // 12845056
            case 8*16*448*448:  t4 = (const float*)d_in[i]; break;   // 25690112
            case 8*256*28*28:   ff = (const float*)d_in[i]; break;   // 1605632
        }
    }

    fused_pool_kernel<<<POOL_BLOCKS, 256>>>(t1, t2, t3, t4);

    constexpr int HALF4 = (NB * 256 * PLANE4) / 2;   // 200704
    combine_kernel<<<(HALF4 + 255) / 256, 256>>>(ff, (float*)d_out);
}